// round 5
// baseline (speedup 1.0000x reference)
#include <cuda_runtime.h>

#define EPSF 1e-8f
#define DEG2RAD 0.017453292519943295f

__device__ double   g_num;    // zero-initialized; self-reset by last block each call
__device__ double   g_den;
__device__ int      g_mask4;
__device__ unsigned g_done;

// ---------------------------------------------------------------------------
// Kernel 1: detect pos_idx storage layout by scanning the first n BYTES
// (safe for u8 / i32 / f32 backing buffers).
//   residue pattern 0b0001 -> int32 {0,1}
//   residue pattern 0b1100 -> float32 {0.0,1.0}
//   anything else / all-zero -> uint8/bool fallback
// g_mask4 starts at 0 (static zero-init on first call, reset by the main
// kernel's last block on every call thereafter).
// ---------------------------------------------------------------------------
__global__ void rot_detect_kernel(const unsigned char* __restrict__ p, int nbytes) {
    int nw = nbytes >> 2;
    const unsigned* w = (const unsigned*)p;
    unsigned pat = 0;
    for (int idx = blockIdx.x * blockDim.x + threadIdx.x; idx < nw;
         idx += gridDim.x * blockDim.x) {
        unsigned v = w[idx];
        if (v & 0x000000FFu) pat |= 1u;
        if (v & 0x0000FF00u) pat |= 2u;
        if (v & 0x00FF0000u) pat |= 4u;
        if (v & 0xFF000000u) pat |= 8u;
    }
    #pragma unroll
    for (int o = 16; o > 0; o >>= 1)
        pat |= __shfl_down_sync(0xffffffffu, pat, o);
    if ((threadIdx.x & 31) == 0 && pat)
        atomicOr(&g_mask4, (int)pat);
}

// ---------------------------------------------------------------------------
// Kernel 2: main — rotated IoU via Sutherland–Hodgman clipping + fused loss
// reduction with last-block finalize (self-resets all device state).
// ---------------------------------------------------------------------------
__global__ void __launch_bounds__(128)
rot_iou_kernel(const float* __restrict__ pred,
               const float* __restrict__ target,
               const void*  __restrict__ pos,
               float* __restrict__ out_loss,
               float* __restrict__ out_iou,
               int n, int has_loss)
{
    int i = blockIdx.x * blockDim.x + threadIdx.x;
    float lnum = 0.0f;
    int   lden = 0;

    if (i < n) {
        const float* p = pred   + 5 * i;
        const float* t = target + 5 * i;

        float x1 = p[0], y1 = p[1], w1 = p[2], h1 = p[3];
        float a1 = p[4] * DEG2RAD;
        float x2 = t[0], y2 = t[1], w2 = t[2], h2 = t[3];
        float a2 = (t[4] * 180.0f - 180.0f) * DEG2RAD;

        float s1, co1, s2, co2;
        __sincosf(a1, &s1, &co1);
        __sincosf(a2, &s2, &co2);

        // CCW corners (same order as reference box2corners)
        const float XS[4] = { 0.5f, -0.5f, -0.5f,  0.5f };
        const float YS[4] = { 0.5f,  0.5f, -0.5f, -0.5f };
        float c1x[4], c1y[4], c2x[4], c2y[4];
        #pragma unroll
        for (int k = 0; k < 4; k++) {
            float xw = XS[k] * w1, yh = YS[k] * h1;
            c1x[k] = xw * co1 - yh * s1 + x1;
            c1y[k] = xw * s1  + yh * co1 + y1;
            xw = XS[k] * w2; yh = YS[k] * h2;
            c2x[k] = xw * co2 - yh * s2 + x2;
            c2y[k] = xw * s2  + yh * co2 + y2;
        }

        // Sutherland–Hodgman: clip box1 polygon by box2's 4 half-planes.
        // CCW polygon -> inside is left of each directed edge (cross >= 0).
        float sxv[8], syv[8];
        #pragma unroll
        for (int k = 0; k < 4; k++) { sxv[k] = c1x[k]; syv[k] = c1y[k]; }
        int cnt = 4;

        #pragma unroll
        for (int e = 0; e < 4; e++) {
            if (cnt) {
                float ax = c2x[e], ay = c2y[e];
                float ex = c2x[(e + 1) & 3] - ax;
                float ey = c2y[(e + 1) & 3] - ay;
                float nx2[8], ny2[8];
                int m = 0;
                float d0 = ex * (syv[0] - ay) - ey * (sxv[0] - ax);
                float dc = d0;
                for (int k = 0; k < cnt; k++) {
                    int k2 = (k + 1 == cnt) ? 0 : k + 1;
                    float dn = (k2 == 0) ? d0
                             : ex * (syv[k2] - ay) - ey * (sxv[k2] - ax);
                    bool ic = (dc >= 0.0f);
                    bool in2 = (dn >= 0.0f);
                    if (ic) { nx2[m] = sxv[k]; ny2[m] = syv[k]; m++; }
                    if (ic != in2) {
                        float tt = __fdividef(dc, dc - dn);
                        nx2[m] = fmaf(tt, sxv[k2] - sxv[k], sxv[k]);
                        ny2[m] = fmaf(tt, syv[k2] - syv[k], syv[k]);
                        m++;
                    }
                    dc = dn;
                }
                for (int k = 0; k < m; k++) { sxv[k] = nx2[k]; syv[k] = ny2[k]; }
                cnt = m;
            }
        }

        float inter = 0.0f;
        if (cnt >= 3) {
            float cr = 0.0f;
            for (int k = 0; k < cnt; k++) {
                int k2 = (k + 1 == cnt) ? 0 : k + 1;
                cr = fmaf(sxv[k], syv[k2], cr) - syv[k] * sxv[k2];
            }
            inter = 0.5f * fabsf(cr);
        }

        float area1 = w1 * h1;
        float area2 = w2 * h2;
        float iou = __fdividef(inter, area1 + area2 - inter + EPSF);
        iou = fminf(fmaxf(iou, 1e-7f), 1.0f - 1e-7f);
        out_iou[i] = iou;

        // mask read per detected layout (uniform branch)
        int m4 = g_mask4;
        bool mm;
        if (m4 == 1)        mm = (((const int*)pos)[i] != 0);
        else if (m4 == 12)  mm = (((const float*)pos)[i] != 0.0f);
        else                mm = (((const unsigned char*)pos)[i] != 0);
        if (mm) { lnum = 1.0f - iou; lden = 1; }
    }

    // warp reduce
    #pragma unroll
    for (int o = 16; o > 0; o >>= 1) {
        lnum += __shfl_down_sync(0xffffffffu, lnum, o);
        lden += __shfl_down_sync(0xffffffffu, lden, o);
    }
    __shared__ float snum[4];
    __shared__ int   sden[4];
    int wid = threadIdx.x >> 5;
    if ((threadIdx.x & 31) == 0) { snum[wid] = lnum; sden[wid] = lden; }
    __syncthreads();
    if (threadIdx.x == 0) {
        float bn = snum[0] + snum[1] + snum[2] + snum[3];
        int   bd = sden[0] + sden[1] + sden[2] + sden[3];
        if (bn != 0.0f) atomicAdd(&g_num, (double)bn);
        if (bd != 0)    atomicAdd(&g_den, (double)bd);
        __threadfence();
        unsigned ticket = atomicAdd(&g_done, 1u);
        if (ticket == gridDim.x - 1) {
            // last block: all partials are in (release via threadfence +
            // atomic ticket). Finalize, then self-reset device state so the
            // next graph replay starts from identical state.
            __threadfence();
            double num = *((volatile double*)&g_num);
            double den = *((volatile double*)&g_den);
            if (den < 1.0) den = 1.0;
            if (has_loss) out_loss[0] = (float)(num / den);
            g_num = 0.0;
            g_den = 0.0;
            g_mask4 = 0;
            g_done = 0u;
        }
    }
}

// ---------------------------------------------------------------------------
extern "C" void kernel_launch(void* const* d_in, const int* in_sizes, int n_in,
                              void* d_out, int out_size)
{
    const float* pred   = (const float*)d_in[0];
    const float* target = (const float*)d_in[1];
    const void*  pos    = d_in[2];
    int n = in_sizes[2];               // pos_idx element count = B*A*W*H

    float* out = (float*)d_out;
    int has_loss = (out_size > n) ? 1 : 0;
    float* out_iou = out + (has_loss ? 1 : 0);

    rot_detect_kernel<<<96, 256>>>((const unsigned char*)pos, n);

    int threads = 128;
    int blocks  = (n + threads - 1) / threads;
    rot_iou_kernel<<<blocks, threads>>>(pred, target, pos, out, out_iou,
                                        n, has_loss);
}

// round 6
// speedup vs baseline: 1.4356x; 1.4356x over previous
#include <cuda_runtime.h>

#define EPSF 1e-8f
#define DEG2RAD 0.017453292519943295f

__device__ double   g_num;    // zero-init; self-reset by last block each call
__device__ double   g_den;
__device__ int      g_mask4;
__device__ unsigned g_done;

// ---------------------------------------------------------------------------
// Kernel 1: detect pos_idx storage layout by scanning the first n BYTES
// (safe for u8 / i32 / f32 backing buffers).
//   residue pattern 0b0001 -> int32 {0,1}
//   residue pattern 0b1100 -> float32 {0.0,1.0}
//   anything else / all-zero -> uint8/bool fallback
// ---------------------------------------------------------------------------
__global__ void rot_detect_kernel(const unsigned char* __restrict__ p, int nbytes) {
    int nw = nbytes >> 2;
    const unsigned* w = (const unsigned*)p;
    unsigned pat = 0;
    for (int idx = blockIdx.x * blockDim.x + threadIdx.x; idx < nw;
         idx += gridDim.x * blockDim.x) {
        unsigned v = w[idx];
        if (v & 0x000000FFu) pat |= 1u;
        if (v & 0x0000FF00u) pat |= 2u;
        if (v & 0x00FF0000u) pat |= 4u;
        if (v & 0xFF000000u) pat |= 8u;
    }
    #pragma unroll
    for (int o = 16; o > 0; o >>= 1)
        pat |= __shfl_down_sync(0xffffffffu, pat, o);
    if ((threadIdx.x & 31) == 0 && pat)
        atomicOr(&g_mask4, (int)pat);
}

// ---------------------------------------------------------------------------
// Order-free intersection area (Green's theorem):
// sum over edges of CCW polygon A of cross(seg_start, seg_end) where seg is
// the part of the edge inside CCW polygon B (Cyrus–Beck interval clip).
// D[e][k] = cross(edge_e of B, A_vertex_k - B_vertex_e); linear in t along
// an A-edge, so dp = D[e][k], slope dr = D[e][k+1] - D[e][k].
// Fully unrolled: all arrays register-resident, branch-free (selects only).
// ---------------------------------------------------------------------------
__device__ __forceinline__ float clip_half_sum(const float ax[4], const float ay[4],
                                               const float bx[4], const float by[4])
{
    float D[4][4];
    #pragma unroll
    for (int e = 0; e < 4; e++) {
        float qx = bx[e], qy = by[e];
        float ex = bx[(e + 1) & 3] - qx;
        float ey = by[(e + 1) & 3] - qy;
        #pragma unroll
        for (int k = 0; k < 4; k++) {
            D[e][k] = ex * (ay[k] - qy) - ey * (ax[k] - qx);
        }
    }

    float acc = 0.0f;
    #pragma unroll
    for (int k = 0; k < 4; k++) {
        int k2 = (k + 1) & 3;
        float px = ax[k], py = ay[k];
        float rx = ax[k2] - px, ry = ay[k2] - py;
        float t0 = 0.0f, t1 = 1.0f;
        bool rej = false;
        #pragma unroll
        for (int e = 0; e < 4; e++) {
            float dp = D[e][k];
            float dr = D[e][k2] - dp;
            float tt = -__fdividef(dp, dr);
            bool par = fabsf(dr) < 1e-12f;
            rej = rej || (par && (dp < 0.0f));
            bool ent = (dr >= 1e-12f);   // d increasing: inside for t >= tt
            bool ext = (dr <= -1e-12f);  // d decreasing: inside for t <= tt
            t0 = ent ? fmaxf(t0, tt) : t0;
            t1 = ext ? fminf(t1, tt) : t1;
        }
        float x0 = fmaf(t0, rx, px), y0 = fmaf(t0, ry, py);
        float x1 = fmaf(t1, rx, px), y1 = fmaf(t1, ry, py);
        float c  = x0 * y1 - y0 * x1;
        acc += (!rej && (t1 > t0)) ? c : 0.0f;
    }
    return acc;
}

// ---------------------------------------------------------------------------
// Kernel 2: main — rotated IoU + fused loss reduction, last-block finalize
// (self-resets all device state for graph replay determinism).
// ---------------------------------------------------------------------------
__global__ void __launch_bounds__(256, 2)
rot_iou_kernel(const float* __restrict__ pred,
               const float* __restrict__ target,
               const void*  __restrict__ pos,
               float* __restrict__ out_loss,
               float* __restrict__ out_iou,
               int n, int has_loss)
{
    int i = blockIdx.x * blockDim.x + threadIdx.x;
    float lnum = 0.0f;
    int   lden = 0;

    if (i < n) {
        const float* p = pred   + 5 * i;
        const float* t = target + 5 * i;

        float x1 = p[0], y1 = p[1], w1 = p[2], h1 = p[3];
        float a1 = p[4] * DEG2RAD;
        float x2 = t[0], y2 = t[1], w2 = t[2], h2 = t[3];
        float a2 = (t[4] * 180.0f - 180.0f) * DEG2RAD;

        float s1, co1, s2, co2;
        __sincosf(a1, &s1, &co1);
        __sincosf(a2, &s2, &co2);

        // CCW corners (same order as reference box2corners)
        const float XS[4] = { 0.5f, -0.5f, -0.5f,  0.5f };
        const float YS[4] = { 0.5f,  0.5f, -0.5f, -0.5f };
        float c1x[4], c1y[4], c2x[4], c2y[4];
        #pragma unroll
        for (int k = 0; k < 4; k++) {
            float xw = XS[k] * w1, yh = YS[k] * h1;
            c1x[k] = xw * co1 - yh * s1 + x1;
            c1y[k] = xw * s1  + yh * co1 + y1;
            xw = XS[k] * w2; yh = YS[k] * h2;
            c2x[k] = xw * co2 - yh * s2 + x2;
            c2y[k] = xw * s2  + yh * co2 + y2;
        }

        float two_area = clip_half_sum(c1x, c1y, c2x, c2y)
                       + clip_half_sum(c2x, c2y, c1x, c1y);
        float inter = fmaxf(0.5f * two_area, 0.0f);

        float area1 = w1 * h1;
        float area2 = w2 * h2;
        float iou = __fdividef(inter, area1 + area2 - inter + EPSF);
        iou = fminf(fmaxf(iou, 1e-7f), 1.0f - 1e-7f);
        out_iou[i] = iou;

        // mask read per detected layout (uniform branch)
        int m4 = g_mask4;
        bool mm;
        if (m4 == 1)        mm = (((const int*)pos)[i] != 0);
        else if (m4 == 12)  mm = (((const float*)pos)[i] != 0.0f);
        else                mm = (((const unsigned char*)pos)[i] != 0);
        if (mm) { lnum = 1.0f - iou; lden = 1; }
    }

    // warp reduce
    #pragma unroll
    for (int o = 16; o > 0; o >>= 1) {
        lnum += __shfl_down_sync(0xffffffffu, lnum, o);
        lden += __shfl_down_sync(0xffffffffu, lden, o);
    }
    __shared__ float snum[8];
    __shared__ int   sden[8];
    int wid = threadIdx.x >> 5;
    if ((threadIdx.x & 31) == 0) { snum[wid] = lnum; sden[wid] = lden; }
    __syncthreads();
    if (threadIdx.x == 0) {
        float bn = 0.0f; int bd = 0;
        int nw = blockDim.x >> 5;
        for (int k = 0; k < nw; k++) { bn += snum[k]; bd += sden[k]; }
        if (bn != 0.0f) atomicAdd(&g_num, (double)bn);
        if (bd != 0)    atomicAdd(&g_den, (double)bd);
        __threadfence();
        unsigned ticket = atomicAdd(&g_done, 1u);
        if (ticket == gridDim.x - 1) {
            __threadfence();
            double num = *((volatile double*)&g_num);
            double den = *((volatile double*)&g_den);
            if (den < 1.0) den = 1.0;
            if (has_loss) out_loss[0] = (float)(num / den);
            g_num = 0.0;
            g_den = 0.0;
            g_mask4 = 0;
            g_done = 0u;
        }
    }
}

// ---------------------------------------------------------------------------
extern "C" void kernel_launch(void* const* d_in, const int* in_sizes, int n_in,
                              void* d_out, int out_size)
{
    const float* pred   = (const float*)d_in[0];
    const float* target = (const float*)d_in[1];
    const void*  pos    = d_in[2];
    int n = in_sizes[2];               // pos_idx element count = B*A*W*H

    float* out = (float*)d_out;
    int has_loss = (out_size > n) ? 1 : 0;
    float* out_iou = out + (has_loss ? 1 : 0);

    rot_detect_kernel<<<96, 256>>>((const unsigned char*)pos, n);

    int threads = 256;
    int blocks  = (n + threads - 1) / threads;
    rot_iou_kernel<<<blocks, threads>>>(pred, target, pos, out, out_iou,
                                        n, has_loss);
}

// round 7
// speedup vs baseline: 2.2329x; 1.5553x over previous
#include <cuda_runtime.h>

#define EPSF 1e-8f
#define DEG2RAD 0.017453292519943295f

__device__ double   g_num;    // zero-init; self-reset by last block each call
__device__ double   g_den;
__device__ int      g_mask4;
__device__ unsigned g_done;

// ---------------------------------------------------------------------------
// Kernel 1: detect pos_idx storage layout by scanning the first n BYTES
// (safe for u8 / i32 / f32 backing buffers).
//   residue pattern 0b0001 -> int32 {0,1}
//   residue pattern 0b1100 -> float32 {0.0,1.0}
//   anything else / all-zero -> uint8/bool fallback
// ---------------------------------------------------------------------------
__global__ void rot_detect_kernel(const unsigned char* __restrict__ p, int nbytes) {
    int nw = nbytes >> 2;
    const unsigned* w = (const unsigned*)p;
    unsigned pat = 0;
    for (int idx = blockIdx.x * blockDim.x + threadIdx.x; idx < nw;
         idx += gridDim.x * blockDim.x) {
        unsigned v = w[idx];
        if (v & 0x000000FFu) pat |= 1u;
        if (v & 0x0000FF00u) pat |= 2u;
        if (v & 0x00FF0000u) pat |= 4u;
        if (v & 0xFF000000u) pat |= 8u;
    }
    #pragma unroll
    for (int o = 16; o > 0; o >>= 1)
        pat |= __shfl_down_sync(0xffffffffu, pat, o);
    if ((threadIdx.x & 31) == 0 && pat)
        atomicOr(&g_mask4, (int)pat);
}

// ---------------------------------------------------------------------------
// Ray-slab clip: fraction of segment p + t*r, t in [0,1], inside the
// axis-aligned box [-Wb,Wb] x [-Hb,Hb]. inf-propagation handles parallel
// edges (outside-parallel -> interval empties -> dt clamps to 0).
// ---------------------------------------------------------------------------
__device__ __forceinline__ float seg_box_dt(float px, float py,
                                            float rx, float ry,
                                            float Wb, float Hb)
{
    float irx = __fdividef(1.0f, rx);
    float iry = __fdividef(1.0f, ry);
    float tx1 = (-Wb - px) * irx;
    float tx2 = ( Wb - px) * irx;
    float ty1 = (-Hb - py) * iry;
    float ty2 = ( Hb - py) * iry;
    float t0 = fmaxf(fmaxf(fminf(tx1, tx2), fminf(ty1, ty2)), 0.0f);
    float t1 = fminf(fminf(fmaxf(tx1, tx2), fmaxf(ty1, ty2)), 1.0f);
    return fmaxf(t1 - t0, 0.0f);
}

// ---------------------------------------------------------------------------
// Kernel 2: main — rotated IoU via frame-local slab clipping + Green's
// theorem (contribution of each clipped edge = cross(p,r)*(t1-t0), exact),
// fused loss reduction with last-block finalize (self-resets device state).
// ---------------------------------------------------------------------------
__global__ void __launch_bounds__(256, 3)
rot_iou_kernel(const float* __restrict__ pred,
               const float* __restrict__ target,
               const void*  __restrict__ pos,
               float* __restrict__ out_loss,
               float* __restrict__ out_iou,
               int n, int has_loss)
{
    int i = blockIdx.x * blockDim.x + threadIdx.x;
    float lnum = 0.0f;
    int   lden = 0;

    if (i < n) {
        const float* p = pred   + 5 * i;
        const float* t = target + 5 * i;

        float x1 = p[0], y1 = p[1], w1 = p[2], h1 = p[3];
        float a1 = p[4] * DEG2RAD;
        float x2 = t[0], y2 = t[1], w2 = t[2], h2 = t[3];
        float a2 = (t[4] * 180.0f - 180.0f) * DEG2RAD;

        float W1 = 0.5f * w1, H1 = 0.5f * h1;
        float W2 = 0.5f * w2, H2 = 0.5f * h2;

        // relative rotation and box1 center in box2's frame
        float sd, cd, s2, c2;
        __sincosf(a1 - a2, &sd, &cd);
        __sincosf(a2,      &s2, &c2);
        float dx = x1 - x2, dy = y1 - y2;
        float ux =  c2 * dx + s2 * dy;
        float uy = -s2 * dx + c2 * dy;

        // box1 edge vectors in box2 frame
        float exx =  w1 * cd, exy = w1 * sd;   // along box1 x-axis
        float eyx = -h1 * sd, eyy = h1 * cd;   // along box1 y-axis

        // box1 corners (CCW, same order as reference) in box2 frame
        float a0x = ux + 0.5f * (exx + eyx), a0y = uy + 0.5f * (exy + eyy);
        float b1x = a0x - exx, b1y = a0y - exy;
        float b2x = b1x - eyx, b2y = b1y - eyy;
        float b3x = a0x - eyx, b3y = a0y - eyy;

        // ---- half 1: box1 edges clipped by box2 slab (box2 frame) ----
        // contribution per edge: cross(p, r) * dt
        float acc1;
        {
            float dt0 = seg_box_dt(a0x, a0y, -exx, -exy, W2, H2);
            float dt1 = seg_box_dt(b1x, b1y, -eyx, -eyy, W2, H2);
            float dt2 = seg_box_dt(b2x, b2y,  exx,  exy, W2, H2);
            float dt3 = seg_box_dt(b3x, b3y,  eyx,  eyy, W2, H2);
            float c0 = a0y * exx - a0x * exy;   // cross(a0, -ex)
            float c1 = b1y * eyx - b1x * eyy;   // cross(b1, -ey)
            float c2c = b2x * exy - b2y * exx;  // cross(b2,  ex)
            float c3 = b3x * eyy - b3y * eyx;   // cross(b3,  ey)
            acc1 = c0 * dt0 + c1 * dt1 + c2c * dt2 + c3 * dt3;
        }

        // ---- half 2: box2 edges clipped by box1 slab (box1 frame) ----
        // every box2 edge has cross(p, r) = W2*h2 in box2's own frame
        float sum2;
        {
            // box2 corner 0 in box1 frame
            float qx = W2 - ux, qy = H2 - uy;
            float g0u =  cd * qx + sd * qy;
            float g0v = -sd * qx + cd * qy;
            // box2 edge vectors in box1 frame
            float fxu = cd * w2, fxv = -sd * w2;   // R(-d)*(w2,0)
            float fyu = sd * h2, fyv =  cd * h2;   // R(-d)*(0,h2)
            float g1u = g0u - fxu, g1v = g0v - fxv;
            float g2u = g1u - fyu, g2v = g1v - fyv;
            float g3u = g0u - fyu, g3v = g0v - fyv;
            float dt0 = seg_box_dt(g0u, g0v, -fxu, -fxv, W1, H1);
            float dt1 = seg_box_dt(g1u, g1v, -fyu, -fyv, W1, H1);
            float dt2 = seg_box_dt(g2u, g2v,  fxu,  fxv, W1, H1);
            float dt3 = seg_box_dt(g3u, g3v,  fyu,  fyv, W1, H1);
            sum2 = (dt0 + dt1) + (dt2 + dt3);
        }

        float inter = fmaxf(0.5f * acc1 + (0.5f * W2 * h2) * sum2, 0.0f);

        float area1 = w1 * h1;
        float area2 = w2 * h2;
        float iou = __fdividef(inter, area1 + area2 - inter + EPSF);
        iou = fminf(fmaxf(iou, 1e-7f), 1.0f - 1e-7f);
        out_iou[i] = iou;

        // mask read per detected layout (uniform branch)
        int m4 = g_mask4;
        bool mm;
        if (m4 == 1)        mm = (((const int*)pos)[i] != 0);
        else if (m4 == 12)  mm = (((const float*)pos)[i] != 0.0f);
        else                mm = (((const unsigned char*)pos)[i] != 0);
        if (mm) { lnum = 1.0f - iou; lden = 1; }
    }

    // warp reduce
    #pragma unroll
    for (int o = 16; o > 0; o >>= 1) {
        lnum += __shfl_down_sync(0xffffffffu, lnum, o);
        lden += __shfl_down_sync(0xffffffffu, lden, o);
    }
    __shared__ float snum[8];
    __shared__ int   sden[8];
    int wid = threadIdx.x >> 5;
    if ((threadIdx.x & 31) == 0) { snum[wid] = lnum; sden[wid] = lden; }
    __syncthreads();
    if (threadIdx.x == 0) {
        float bn = 0.0f; int bd = 0;
        int nw = blockDim.x >> 5;
        for (int k = 0; k < nw; k++) { bn += snum[k]; bd += sden[k]; }
        if (bn != 0.0f) atomicAdd(&g_num, (double)bn);
        if (bd != 0)    atomicAdd(&g_den, (double)bd);
        __threadfence();
        unsigned ticket = atomicAdd(&g_done, 1u);
        if (ticket == gridDim.x - 1) {
            __threadfence();
            double num = *((volatile double*)&g_num);
            double den = *((volatile double*)&g_den);
            if (den < 1.0) den = 1.0;
            if (has_loss) out_loss[0] = (float)(num / den);
            g_num = 0.0;
            g_den = 0.0;
            g_mask4 = 0;
            g_done = 0u;
        }
    }
}

// ---------------------------------------------------------------------------
extern "C" void kernel_launch(void* const* d_in, const int* in_sizes, int n_in,
                              void* d_out, int out_size)
{
    const float* pred   = (const float*)d_in[0];
    const float* target = (const float*)d_in[1];
    const void*  pos    = d_in[2];
    int n = in_sizes[2];               // pos_idx element count = B*A*W*H

    float* out = (float*)d_out;
    int has_loss = (out_size > n) ? 1 : 0;
    float* out_iou = out + (has_loss ? 1 : 0);

    rot_detect_kernel<<<96, 256>>>((const unsigned char*)pos, n);

    int threads = 256;
    int blocks  = (n + threads - 1) / threads;
    rot_iou_kernel<<<blocks, threads>>>(pred, target, pos, out, out_iou,
                                        n, has_loss);
}

// round 8
// speedup vs baseline: 3.2222x; 1.4431x over previous
#include <cuda_runtime.h>

#define EPSF 1e-8f
#define DEG2RAD 0.017453292519943295f

__device__ double   g_num;    // zero-init; self-reset by last block each call
__device__ double   g_den;
__device__ int      g_mask4;
__device__ unsigned g_done;

// ---------------------------------------------------------------------------
// Kernel 1: detect pos_idx storage layout by scanning the first n BYTES
// (safe for u8 / i32 / f32 backing buffers).
//   residue pattern 0b0001 -> int32 {0,1}
//   residue pattern 0b1100 -> float32 {0.0,1.0}
//   anything else / all-zero -> uint8/bool fallback
// ---------------------------------------------------------------------------
__global__ void rot_detect_kernel(const unsigned char* __restrict__ p, int nbytes) {
    int nw = nbytes >> 2;
    const unsigned* w = (const unsigned*)p;
    unsigned pat = 0;
    for (int idx = blockIdx.x * blockDim.x + threadIdx.x; idx < nw;
         idx += gridDim.x * blockDim.x) {
        unsigned v = w[idx];
        if (v & 0x000000FFu) pat |= 1u;
        if (v & 0x0000FF00u) pat |= 2u;
        if (v & 0x00FF0000u) pat |= 4u;
        if (v & 0xFF000000u) pat |= 8u;
    }
    #pragma unroll
    for (int o = 16; o > 0; o >>= 1)
        pat |= __shfl_down_sync(0xffffffffu, pat, o);
    if ((threadIdx.x & 31) == 0 && pat)
        atomicOr(&g_mask4, (int)pat);
}

// ---------------------------------------------------------------------------
// Slab clip with precomputed (signed) reciprocal of the edge direction:
// fraction of segment p + t*r, t in [0,1], inside [-Wb,Wb] x [-Hb,Hb].
// inf-propagation handles parallel edges (outside-parallel -> empty interval).
// ---------------------------------------------------------------------------
__device__ __forceinline__ float seg_dt(float px, float py,
                                        float irx, float iry,
                                        float Wb, float Hb)
{
    float tx1 = (-Wb - px) * irx;
    float tx2 = ( Wb - px) * irx;
    float ty1 = (-Hb - py) * iry;
    float ty2 = ( Hb - py) * iry;
    float t0 = fmaxf(fmaxf(fminf(tx1, tx2), fminf(ty1, ty2)), 0.0f);
    float t1 = fminf(fminf(fmaxf(tx1, tx2), fmaxf(ty1, ty2)), 1.0f);
    return fmaxf(t1 - t0, 0.0f);
}

// ---------------------------------------------------------------------------
// One rotated-IoU: frame-local slab clipping + Green's theorem.
// b1 = pred record (5 floats), b2 = target record (5 floats).
// ---------------------------------------------------------------------------
__device__ __forceinline__ float compute_iou(const float* b1, const float* b2)
{
    float x1 = b1[0], y1 = b1[1], w1 = b1[2], h1 = b1[3];
    float a1 = b1[4] * DEG2RAD;
    float x2 = b2[0], y2 = b2[1], w2 = b2[2], h2 = b2[3];
    float a2 = (b2[4] * 180.0f - 180.0f) * DEG2RAD;

    float W1 = 0.5f * w1, H1 = 0.5f * h1;
    float W2 = 0.5f * w2, H2 = 0.5f * h2;

    float sd, cd, s2, c2;
    __sincosf(a1 - a2, &sd, &cd);
    __sincosf(a2,      &s2, &c2);
    float dx = x1 - x2, dy = y1 - y2;
    float ux =  c2 * dx + s2 * dy;
    float uy = -s2 * dx + c2 * dy;

    // box1 edge vectors / corners (CCW) in box2 frame
    float exx =  w1 * cd, exy = w1 * sd;
    float eyx = -h1 * sd, eyy = h1 * cd;
    float a0x = ux + 0.5f * (exx + eyx), a0y = uy + 0.5f * (exy + eyy);
    float b1x = a0x - exx, b1y = a0y - exy;
    float b2x = b1x - eyx, b2y = b1y - eyy;
    float b3x = a0x - eyx, b3y = a0y - eyy;

    // shared reciprocals for the two parallel edge pairs
    float iexx = __fdividef(1.0f, exx), iexy = __fdividef(1.0f, exy);
    float ieyx = __fdividef(1.0f, eyx), ieyy = __fdividef(1.0f, eyy);

    // half 1: box1 edges clipped by box2 slab; contribution cross(p,r)*dt
    float dt0 = seg_dt(a0x, a0y, -iexx, -iexy, W2, H2);
    float dt1 = seg_dt(b1x, b1y, -ieyx, -ieyy, W2, H2);
    float dt2 = seg_dt(b2x, b2y,  iexx,  iexy, W2, H2);
    float dt3 = seg_dt(b3x, b3y,  ieyx,  ieyy, W2, H2);
    float c0  = a0y * exx - a0x * exy;   // cross(a0, -ex)
    float c1  = b1y * eyx - b1x * eyy;   // cross(b1, -ey)
    float c2c = b2x * exy - b2y * exx;   // cross(b2,  ex)
    float c3  = b3x * eyy - b3y * eyx;   // cross(b3,  ey)
    float acc1 = c0 * dt0 + c1 * dt1 + c2c * dt2 + c3 * dt3;

    // half 2: box2 edges clipped by box1 slab (box1 frame);
    // every box2 edge contributes the constant cross W2*h2 per unit dt
    float qx = W2 - ux, qy = H2 - uy;
    float g0u =  cd * qx + sd * qy;
    float g0v = -sd * qx + cd * qy;
    float fxu = cd * w2, fxv = -sd * w2;
    float fyu = sd * h2, fyv =  cd * h2;
    float g1u = g0u - fxu, g1v = g0v - fxv;
    float g2u = g1u - fyu, g2v = g1v - fyv;
    float g3u = g0u - fyu, g3v = g0v - fyv;
    float ifxu = __fdividef(1.0f, fxu), ifxv = __fdividef(1.0f, fxv);
    float ifyu = __fdividef(1.0f, fyu), ifyv = __fdividef(1.0f, fyv);
    float e0 = seg_dt(g0u, g0v, -ifxu, -ifxv, W1, H1);
    float e1 = seg_dt(g1u, g1v, -ifyu, -ifyv, W1, H1);
    float e2 = seg_dt(g2u, g2v,  ifxu,  ifxv, W1, H1);
    float e3 = seg_dt(g3u, g3v,  ifyu,  ifyv, W1, H1);
    float sum2 = (e0 + e1) + (e2 + e3);

    float inter = fmaxf(0.5f * acc1 + (0.5f * W2 * h2) * sum2, 0.0f);
    float iou = __fdividef(inter, w1 * h1 + w2 * h2 - inter + EPSF);
    return fminf(fmaxf(iou, 1e-7f), 1.0f - 1e-7f);
}

// ---------------------------------------------------------------------------
// Kernel 2: main — 4 elements per thread, vectorized float4 loads,
// fused loss reduction with last-block finalize (self-resets device state).
// ---------------------------------------------------------------------------
__global__ void __launch_bounds__(256, 2)
rot_iou_kernel(const float* __restrict__ pred,
               const float* __restrict__ target,
               const void*  __restrict__ pos,
               float* __restrict__ out_loss,
               float* __restrict__ out_iou,
               int n, int has_loss)
{
    int t4 = blockIdx.x * blockDim.x + threadIdx.x;   // group of 4 elements
    int e0 = t4 * 4;
    float lnum = 0.0f;
    int   lden = 0;

    if (e0 < n) {
        int m4 = g_mask4;
        if (e0 + 4 <= n) {
            // 4 records = 80B = 5 x float4, 16B-aligned
            const float4* P = (const float4*)pred   + 5 * t4;
            const float4* T = (const float4*)target + 5 * t4;
            float pf[20], tf[20];
            #pragma unroll
            for (int k = 0; k < 5; k++) {
                float4 v = P[k];
                pf[4*k] = v.x; pf[4*k+1] = v.y; pf[4*k+2] = v.z; pf[4*k+3] = v.w;
            }
            #pragma unroll
            for (int k = 0; k < 5; k++) {
                float4 v = T[k];
                tf[4*k] = v.x; tf[4*k+1] = v.y; tf[4*k+2] = v.z; tf[4*k+3] = v.w;
            }
            unsigned mbits;
            if (m4 == 1) {
                uint4 mv = ((const uint4*)pos)[t4];
                mbits = (mv.x ? 1u : 0u) | (mv.y ? 2u : 0u) |
                        (mv.z ? 4u : 0u) | (mv.w ? 8u : 0u);
            } else if (m4 == 12) {
                float4 mv = ((const float4*)pos)[t4];
                mbits = (mv.x != 0.0f ? 1u : 0u) | (mv.y != 0.0f ? 2u : 0u) |
                        (mv.z != 0.0f ? 4u : 0u) | (mv.w != 0.0f ? 8u : 0u);
            } else {
                unsigned mv = ((const unsigned*)pos)[t4];
                mbits = ((mv & 0x000000FFu) ? 1u : 0u) |
                        ((mv & 0x0000FF00u) ? 2u : 0u) |
                        ((mv & 0x00FF0000u) ? 4u : 0u) |
                        ((mv & 0xFF000000u) ? 8u : 0u);
            }
            #pragma unroll
            for (int j = 0; j < 4; j++) {
                float iou = compute_iou(pf + 5 * j, tf + 5 * j);
                out_iou[e0 + j] = iou;
                if ((mbits >> j) & 1u) { lnum += 1.0f - iou; lden++; }
            }
        } else {
            // scalar tail (n not divisible by 4)
            for (int j = 0; j < 4 && e0 + j < n; j++) {
                int i = e0 + j;
                float pb[5], tb[5];
                #pragma unroll
                for (int k = 0; k < 5; k++) {
                    pb[k] = pred[5 * i + k];
                    tb[k] = target[5 * i + k];
                }
                float iou = compute_iou(pb, tb);
                out_iou[i] = iou;
                bool mm;
                if (m4 == 1)       mm = (((const int*)pos)[i] != 0);
                else if (m4 == 12) mm = (((const float*)pos)[i] != 0.0f);
                else               mm = (((const unsigned char*)pos)[i] != 0);
                if (mm) { lnum += 1.0f - iou; lden++; }
            }
        }
    }

    // warp reduce
    #pragma unroll
    for (int o = 16; o > 0; o >>= 1) {
        lnum += __shfl_down_sync(0xffffffffu, lnum, o);
        lden += __shfl_down_sync(0xffffffffu, lden, o);
    }
    __shared__ float snum[8];
    __shared__ int   sden[8];
    int wid = threadIdx.x >> 5;
    if ((threadIdx.x & 31) == 0) { snum[wid] = lnum; sden[wid] = lden; }
    __syncthreads();
    if (threadIdx.x == 0) {
        float bn = 0.0f; int bd = 0;
        int nw = blockDim.x >> 5;
        for (int k = 0; k < nw; k++) { bn += snum[k]; bd += sden[k]; }
        if (bn != 0.0f) atomicAdd(&g_num, (double)bn);
        if (bd != 0)    atomicAdd(&g_den, (double)bd);
        __threadfence();
        unsigned ticket = atomicAdd(&g_done, 1u);
        if (ticket == gridDim.x - 1) {
            __threadfence();
            double num = *((volatile double*)&g_num);
            double den = *((volatile double*)&g_den);
            if (den < 1.0) den = 1.0;
            if (has_loss) out_loss[0] = (float)(num / den);
            g_num = 0.0;
            g_den = 0.0;
            g_mask4 = 0;
            g_done = 0u;
        }
    }
}

// ---------------------------------------------------------------------------
extern "C" void kernel_launch(void* const* d_in, const int* in_sizes, int n_in,
                              void* d_out, int out_size)
{
    const float* pred   = (const float*)d_in[0];
    const float* target = (const float*)d_in[1];
    const void*  pos    = d_in[2];
    int n = in_sizes[2];               // pos_idx element count = B*A*W*H

    float* out = (float*)d_out;
    int has_loss = (out_size > n) ? 1 : 0;
    float* out_iou = out + (has_loss ? 1 : 0);

    rot_detect_kernel<<<96, 256>>>((const unsigned char*)pos, n);

    int nt4     = (n + 3) / 4;
    int threads = 256;
    int blocks  = (nt4 + threads - 1) / threads;
    rot_iou_kernel<<<blocks, threads>>>(pred, target, pos, out, out_iou,
                                        n, has_loss);
}

// round 9
// speedup vs baseline: 3.3819x; 1.0496x over previous
#include <cuda_runtime.h>

#define EPSF 1e-8f
#define DEG2RAD 0.017453292519943295f

#define TPB   256
#define EPT   2                  // elements per thread
#define EPB   (TPB * EPT)        // 512 elements per block

__device__ double   g_num;    // zero-init; self-reset by last block each call
__device__ double   g_den;
__device__ int      g_mask4;
__device__ unsigned g_done;

// ---------------------------------------------------------------------------
// Kernel 1: detect pos_idx storage layout by scanning the first n BYTES
// (safe for u8 / i32 / f32 backing buffers).
//   residue pattern 0b0001 -> int32 {0,1}
//   residue pattern 0b1100 -> float32 {0.0,1.0}
//   anything else / all-zero -> uint8/bool fallback
// ---------------------------------------------------------------------------
__global__ void rot_detect_kernel(const unsigned char* __restrict__ p, int nbytes) {
    int nw = nbytes >> 2;
    const unsigned* w = (const unsigned*)p;
    unsigned pat = 0;
    for (int idx = blockIdx.x * blockDim.x + threadIdx.x; idx < nw;
         idx += gridDim.x * blockDim.x) {
        unsigned v = w[idx];
        if (v & 0x000000FFu) pat |= 1u;
        if (v & 0x0000FF00u) pat |= 2u;
        if (v & 0x00FF0000u) pat |= 4u;
        if (v & 0xFF000000u) pat |= 8u;
    }
    #pragma unroll
    for (int o = 16; o > 0; o >>= 1)
        pat |= __shfl_down_sync(0xffffffffu, pat, o);
    if ((threadIdx.x & 31) == 0 && pat)
        atomicOr(&g_mask4, (int)pat);
}

// ---------------------------------------------------------------------------
// Slab clip with precomputed reciprocal: fraction of segment p + t*r,
// t in [0,1], inside [-Wb,Wb] x [-Hb,Hb]. inf-propagation handles parallel
// edges (outside-parallel -> empty interval -> dt clamps to 0).
// ---------------------------------------------------------------------------
__device__ __forceinline__ float seg_dt(float px, float py,
                                        float irx, float iry,
                                        float Wb, float Hb)
{
    float tx1 = (-Wb - px) * irx;
    float tx2 = ( Wb - px) * irx;
    float ty1 = (-Hb - py) * iry;
    float ty2 = ( Hb - py) * iry;
    float t0 = fmaxf(fmaxf(fminf(tx1, tx2), fminf(ty1, ty2)), 0.0f);
    float t1 = fminf(fminf(fmaxf(tx1, tx2), fmaxf(ty1, ty2)), 1.0f);
    return fmaxf(t1 - t0, 0.0f);
}

// ---------------------------------------------------------------------------
// One rotated-IoU: frame-local slab clipping + Green's theorem.
// ---------------------------------------------------------------------------
__device__ __forceinline__ float compute_iou(float x1, float y1, float w1,
                                             float h1, float a1raw,
                                             float x2, float y2, float w2,
                                             float h2, float a2raw)
{
    float a1 = a1raw * DEG2RAD;
    float a2 = (a2raw * 180.0f - 180.0f) * DEG2RAD;

    float W1 = 0.5f * w1, H1 = 0.5f * h1;
    float W2 = 0.5f * w2, H2 = 0.5f * h2;

    float sd, cd, s2, c2;
    __sincosf(a1 - a2, &sd, &cd);
    __sincosf(a2,      &s2, &c2);
    float dx = x1 - x2, dy = y1 - y2;
    float ux =  c2 * dx + s2 * dy;
    float uy = -s2 * dx + c2 * dy;

    // box1 edge vectors / corners (CCW) in box2 frame
    float exx =  w1 * cd, exy = w1 * sd;
    float eyx = -h1 * sd, eyy = h1 * cd;
    float a0x = ux + 0.5f * (exx + eyx), a0y = uy + 0.5f * (exy + eyy);
    float b1x = a0x - exx, b1y = a0y - exy;
    float b2x = b1x - eyx, b2y = b1y - eyy;
    float b3x = a0x - eyx, b3y = a0y - eyy;

    // shared reciprocals for the two parallel edge pairs
    float iexx = __fdividef(1.0f, exx), iexy = __fdividef(1.0f, exy);
    float ieyx = __fdividef(1.0f, eyx), ieyy = __fdividef(1.0f, eyy);

    // half 1: box1 edges clipped by box2 slab; contribution cross(p,r)*dt
    float dt0 = seg_dt(a0x, a0y, -iexx, -iexy, W2, H2);
    float dt1 = seg_dt(b1x, b1y, -ieyx, -ieyy, W2, H2);
    float dt2 = seg_dt(b2x, b2y,  iexx,  iexy, W2, H2);
    float dt3 = seg_dt(b3x, b3y,  ieyx,  ieyy, W2, H2);
    float c0  = a0y * exx - a0x * exy;
    float c1  = b1y * eyx - b1x * eyy;
    float c2c = b2x * exy - b2y * exx;
    float c3  = b3x * eyy - b3y * eyx;
    float acc1 = c0 * dt0 + c1 * dt1 + c2c * dt2 + c3 * dt3;

    // half 2: box2 edges clipped by box1 slab (box1 frame);
    // every box2 edge contributes the constant cross W2*h2 per unit dt
    float qx = W2 - ux, qy = H2 - uy;
    float g0u =  cd * qx + sd * qy;
    float g0v = -sd * qx + cd * qy;
    float fxu = cd * w2, fxv = -sd * w2;
    float fyu = sd * h2, fyv =  cd * h2;
    float g1u = g0u - fxu, g1v = g0v - fxv;
    float g2u = g1u - fyu, g2v = g1v - fyv;
    float g3u = g0u - fyu, g3v = g0v - fyv;
    float ifxu = __fdividef(1.0f, fxu), ifxv = __fdividef(1.0f, fxv);
    float ifyu = __fdividef(1.0f, fyu), ifyv = __fdividef(1.0f, fyv);
    float e0 = seg_dt(g0u, g0v, -ifxu, -ifxv, W1, H1);
    float e1 = seg_dt(g1u, g1v, -ifyu, -ifyv, W1, H1);
    float e2 = seg_dt(g2u, g2v,  ifxu,  ifxv, W1, H1);
    float e3 = seg_dt(g3u, g3v,  ifyu,  ifyv, W1, H1);
    float sum2 = (e0 + e1) + (e2 + e3);

    float inter = fmaxf(0.5f * acc1 + (0.5f * W2 * h2) * sum2, 0.0f);
    float iou = __fdividef(inter, w1 * h1 + w2 * h2 - inter + EPSF);
    return fminf(fmaxf(iou, 1e-7f), 1.0f - 1e-7f);
}

// ---------------------------------------------------------------------------
// Kernel 2: main — smem-staged coalesced loads, 2 elements/thread serial
// compute (low regs, high occupancy), fused loss reduction + last-block
// finalize (self-resets device state for graph replay determinism).
// ---------------------------------------------------------------------------
__global__ void __launch_bounds__(TPB, 3)
rot_iou_kernel(const float* __restrict__ pred,
               const float* __restrict__ target,
               const void*  __restrict__ pos,
               float* __restrict__ out_loss,
               float* __restrict__ out_iou,
               int n, int has_loss)
{
    __shared__ float sp[EPB * 5];     // 10240 B
    __shared__ float st[EPB * 5];     // 10240 B

    int tid = threadIdx.x;
    int e0  = blockIdx.x * EPB;       // first element of this block
    int cnt = n - e0;
    if (cnt > EPB) cnt = EPB;

    // ---- stage pred/target tiles with coalesced loads ----
    if (cnt == EPB) {
        // full tile: 2560 floats = 640 float4 per array, 16B-aligned
        const float4* P = (const float4*)(pred   + (size_t)e0 * 5);
        const float4* T = (const float4*)(target + (size_t)e0 * 5);
        float4* SP = (float4*)sp;
        float4* ST = (float4*)st;
        #pragma unroll
        for (int k = 0; k < 2; k++) {
            int idx = tid + k * TPB;
            SP[idx] = P[idx];
            ST[idx] = T[idx];
        }
        {
            int idx = tid + 2 * TPB;
            if (idx < EPB * 5 / 4) { SP[idx] = P[idx]; ST[idx] = T[idx]; }
        }
    } else if (cnt > 0) {
        int nf = cnt * 5;
        const float* P = pred   + (size_t)e0 * 5;
        const float* T = target + (size_t)e0 * 5;
        for (int idx = tid; idx < nf; idx += TPB) {
            sp[idx] = P[idx];
            st[idx] = T[idx];
        }
    }
    __syncthreads();

    float lnum = 0.0f;
    int   lden = 0;
    int   m4   = g_mask4;

    #pragma unroll
    for (int j = 0; j < EPT; j++) {
        int el = tid + j * TPB;        // local element (stride-TPB sets)
        int e  = e0 + el;
        if (el < cnt) {
            const float* pb = sp + 5 * el;
            const float* tb = st + 5 * el;
            float iou = compute_iou(pb[0], pb[1], pb[2], pb[3], pb[4],
                                    tb[0], tb[1], tb[2], tb[3], tb[4]);
            out_iou[e] = iou;
            bool mm;
            if (m4 == 1)       mm = (((const int*)pos)[e] != 0);
            else if (m4 == 12) mm = (((const float*)pos)[e] != 0.0f);
            else               mm = (((const unsigned char*)pos)[e] != 0);
            if (mm) { lnum += 1.0f - iou; lden++; }
        }
    }

    // warp reduce
    #pragma unroll
    for (int o = 16; o > 0; o >>= 1) {
        lnum += __shfl_down_sync(0xffffffffu, lnum, o);
        lden += __shfl_down_sync(0xffffffffu, lden, o);
    }
    __shared__ float snum[TPB / 32];
    __shared__ int   sden[TPB / 32];
    int wid = tid >> 5;
    if ((tid & 31) == 0) { snum[wid] = lnum; sden[wid] = lden; }
    __syncthreads();
    if (tid == 0) {
        float bn = 0.0f; int bd = 0;
        #pragma unroll
        for (int k = 0; k < TPB / 32; k++) { bn += snum[k]; bd += sden[k]; }
        if (bn != 0.0f) atomicAdd(&g_num, (double)bn);
        if (bd != 0)    atomicAdd(&g_den, (double)bd);
        __threadfence();
        unsigned ticket = atomicAdd(&g_done, 1u);
        if (ticket == gridDim.x - 1) {
            __threadfence();
            double num = *((volatile double*)&g_num);
            double den = *((volatile double*)&g_den);
            if (den < 1.0) den = 1.0;
            if (has_loss) out_loss[0] = (float)(num / den);
            g_num = 0.0;
            g_den = 0.0;
            g_mask4 = 0;
            g_done = 0u;
        }
    }
}

// ---------------------------------------------------------------------------
extern "C" void kernel_launch(void* const* d_in, const int* in_sizes, int n_in,
                              void* d_out, int out_size)
{
    const float* pred   = (const float*)d_in[0];
    const float* target = (const float*)d_in[1];
    const void*  pos    = d_in[2];
    int n = in_sizes[2];               // pos_idx element count = B*A*W*H

    float* out = (float*)d_out;
    int has_loss = (out_size > n) ? 1 : 0;
    float* out_iou = out + (has_loss ? 1 : 0);

    rot_detect_kernel<<<96, 256>>>((const unsigned char*)pos, n);

    int blocks = (n + EPB - 1) / EPB;
    rot_iou_kernel<<<blocks, TPB>>>(pred, target, pos, out, out_iou,
                                    n, has_loss);
}

// round 10
// speedup vs baseline: 3.7908x; 1.1209x over previous
#include <cuda_runtime.h>

#define EPSF 1e-8f
#define DEG2RAD 0.017453292519943295f

#define TPB   256
#define EPT   4                  // elements per thread
#define EPB   (TPB * EPT)        // 1024 elements per block

__device__ double   g_num;    // zero-init; self-reset by last block each call
__device__ double   g_den;
__device__ int      g_mask4;
__device__ unsigned g_done;

// ---------------------------------------------------------------------------
// Kernel 1: detect pos_idx storage layout by scanning the first n BYTES
// (safe for u8 / i32 / f32 backing buffers).
//   residue pattern 0b0001 -> int32 {0,1}
//   residue pattern 0b1100 -> float32 {0.0,1.0}
//   anything else / all-zero -> uint8/bool fallback
// ---------------------------------------------------------------------------
__global__ void rot_detect_kernel(const unsigned char* __restrict__ p, int nbytes) {
    int nw = nbytes >> 2;
    const unsigned* w = (const unsigned*)p;
    unsigned pat = 0;
    for (int idx = blockIdx.x * blockDim.x + threadIdx.x; idx < nw;
         idx += gridDim.x * blockDim.x) {
        unsigned v = w[idx];
        if (v & 0x000000FFu) pat |= 1u;
        if (v & 0x0000FF00u) pat |= 2u;
        if (v & 0x00FF0000u) pat |= 4u;
        if (v & 0xFF000000u) pat |= 8u;
    }
    #pragma unroll
    for (int o = 16; o > 0; o >>= 1)
        pat |= __shfl_down_sync(0xffffffffu, pat, o);
    if ((threadIdx.x & 31) == 0 && pat)
        atomicOr(&g_mask4, (int)pat);
}

// ---------------------------------------------------------------------------
// SCALED slab clip: returns dt*s, where dt is the fraction of segment
// p + t*r (t in [0,1]) inside [-Wb,Wb] x [-Hb,Hb], s = |rx|*|ry|.
// kx = copysign(|ry|, rx), ky = copysign(|rx|, ry). Division-free; no infs.
// ---------------------------------------------------------------------------
__device__ __forceinline__ float seg_dts(float px, float py,
                                         float kx, float ky,
                                         float Wb, float Hb, float s)
{
    float u1 = (-Wb - px) * kx;
    float u2 = ( Wb - px) * kx;
    float v1 = (-Hb - py) * ky;
    float v2 = ( Hb - py) * ky;
    float t0 = fmaxf(fmaxf(fminf(u1, u2), fminf(v1, v2)), 0.0f);
    float t1 = fminf(fminf(fmaxf(u1, u2), fmaxf(v1, v2)), s);
    return fmaxf(t1 - t0, 0.0f);
}

// ---------------------------------------------------------------------------
// One rotated-IoU: frame-local scaled slab clipping + Green's theorem.
// Only 3 divisions + 2 sincos of MUFU work per element.
// ---------------------------------------------------------------------------
__device__ __forceinline__ float compute_iou(float x1, float y1, float w1,
                                             float h1, float a1raw,
                                             float x2, float y2, float w2,
                                             float h2, float a2raw)
{
    float a1 = a1raw * DEG2RAD;
    float a2 = (a2raw * 180.0f - 180.0f) * DEG2RAD;

    float W1 = 0.5f * w1, H1 = 0.5f * h1;
    float W2 = 0.5f * w2, H2 = 0.5f * h2;

    float sd, cd, s2, c2;
    __sincosf(a1 - a2, &sd, &cd);
    __sincosf(a2,      &s2, &c2);
    float dx = x1 - x2, dy = y1 - y2;
    float ux =  c2 * dx + s2 * dy;
    float uy = -s2 * dx + c2 * dy;

    // box1 edge vectors / corners (CCW) in box2 frame
    float exx =  w1 * cd, exy = w1 * sd;
    float eyx = -h1 * sd, eyy = h1 * cd;
    float a0x = ux + 0.5f * (exx + eyx), a0y = uy + 0.5f * (exy + eyy);
    float b1x = a0x - exx, b1y = a0y - exy;
    float b2x = b1x - eyx, b2y = b1y - eyy;
    float b3x = a0x - eyx, b3y = a0y - eyy;

    // shared scale factors: all |edge|-products reduce to kappa = |sd*cd|
    float ts = fabsf(sd), tc = fabsf(cd);
    float kap = ts * tc;
    float alp = copysignf(ts, cd);    // |sd| * sgn(cd)
    float bet = copysignf(tc, sd);    // |cd| * sgn(sd)
    float sA = (w1 * w1) * kap;       // for +-ex edges
    float sB = (h1 * h1) * kap;       // for +-ey edges
    float kxA = w1 * alp, kyA = w1 * bet;
    float kxB = -h1 * bet, kyB = h1 * alp;

    // half 1: box1 edges clipped by box2 slab; contribution cross(p,r)*dt
    float dts0 = seg_dts(a0x, a0y, -kxA, -kyA, W2, H2, sA);
    float dts1 = seg_dts(b1x, b1y, -kxB, -kyB, W2, H2, sB);
    float dts2 = seg_dts(b2x, b2y,  kxA,  kyA, W2, H2, sA);
    float dts3 = seg_dts(b3x, b3y,  kxB,  kyB, W2, H2, sB);
    float c0  = a0y * exx - a0x * exy;
    float c1  = b1y * eyx - b1x * eyy;
    float c2c = b2x * exy - b2y * exx;
    float c3  = b3x * eyy - b3y * eyx;
    float PA = c0 * dts0 + c2c * dts2;
    float PB = c1 * dts1 + c3 * dts3;
    float acc1 = __fdividef(PA * sB + PB * sA, fmaxf(sA * sB, 1e-35f));

    // half 2: box2 edges clipped by box1 slab (box1 frame);
    // every box2 edge contributes the constant cross w2*h2/2 per unit dt
    float qx = W2 - ux, qy = H2 - uy;
    float g0u =  cd * qx + sd * qy;
    float g0v = -sd * qx + cd * qy;
    float fxu = cd * w2, fxv = -sd * w2;
    float fyu = sd * h2, fyv =  cd * h2;
    float g1u = g0u - fxu, g1v = g0v - fxv;
    float g2u = g1u - fyu, g2v = g1v - fyv;
    float g3u = g0u - fyu, g3v = g0v - fyv;
    float sC = (w2 * w2) * kap;
    float sD = (h2 * h2) * kap;
    float kxC = w2 * alp, kyC = -w2 * bet;
    float kxD = h2 * bet, kyD =  h2 * alp;
    float e0 = seg_dts(g0u, g0v, -kxC, -kyC, W1, H1, sC);
    float e1 = seg_dts(g1u, g1v, -kxD, -kyD, W1, H1, sD);
    float e2 = seg_dts(g2u, g2v,  kxC,  kyC, W1, H1, sC);
    float e3 = seg_dts(g3u, g3v,  kxD,  kyD, W1, H1, sD);
    float SC = e0 + e2, SD = e1 + e3;
    float sum2 = __fdividef(SC * sD + SD * sC, fmaxf(sC * sD, 1e-35f));

    float inter = fmaxf(0.5f * acc1 + (0.25f * w2 * h2) * sum2, 0.0f);
    float iou = __fdividef(inter, w1 * h1 + w2 * h2 - inter + EPSF);
    return fminf(fmaxf(iou, 1e-7f), 1.0f - 1e-7f);
}

// ---------------------------------------------------------------------------
// Kernel 2: main — smem-staged coalesced loads, 4 elements/thread serial
// compute, single-wave grid, fused loss reduction + last-block finalize
// (self-resets device state for graph replay determinism).
// ---------------------------------------------------------------------------
__global__ void __launch_bounds__(TPB, 5)
rot_iou_kernel(const float* __restrict__ pred,
               const float* __restrict__ target,
               const void*  __restrict__ pos,
               float* __restrict__ out_loss,
               float* __restrict__ out_iou,
               int n, int has_loss)
{
    __shared__ float sp[EPB * 5];     // 20 KB
    __shared__ float st[EPB * 5];     // 20 KB

    int tid = threadIdx.x;
    int e0  = blockIdx.x * EPB;       // first element of this block
    int cnt = n - e0;
    if (cnt > EPB) cnt = EPB;
    int m4 = g_mask4;

    // ---- stage pred/target tiles with coalesced loads ----
    if (cnt == EPB) {
        // full tile: 5120 floats = 1280 float4 per array (1280/TPB = 5 exact)
        const float4* P = (const float4*)(pred   + (size_t)e0 * 5);
        const float4* T = (const float4*)(target + (size_t)e0 * 5);
        float4* SP = (float4*)sp;
        float4* ST = (float4*)st;
        #pragma unroll
        for (int k = 0; k < 5; k++) {
            int idx = tid + k * TPB;
            SP[idx] = P[idx];
            ST[idx] = T[idx];
        }
    } else if (cnt > 0) {
        int nf = cnt * 5;
        const float* P = pred   + (size_t)e0 * 5;
        const float* T = target + (size_t)e0 * 5;
        for (int idx = tid; idx < nf; idx += TPB) {
            sp[idx] = P[idx];
            st[idx] = T[idx];
        }
    }
    __syncthreads();

    float lnum = 0.0f;
    int   lden = 0;

    #pragma unroll
    for (int j = 0; j < EPT; j++) {
        int el = tid + j * TPB;        // local element (stride-TPB sets)
        int e  = e0 + el;
        if (el < cnt) {
            const float* pb = sp + 5 * el;
            const float* tb = st + 5 * el;
            float iou = compute_iou(pb[0], pb[1], pb[2], pb[3], pb[4],
                                    tb[0], tb[1], tb[2], tb[3], tb[4]);
            out_iou[e] = iou;
            bool mm;
            if (m4 == 1)       mm = (((const int*)pos)[e] != 0);
            else if (m4 == 12) mm = (((const float*)pos)[e] != 0.0f);
            else               mm = (((const unsigned char*)pos)[e] != 0);
            if (mm) { lnum += 1.0f - iou; lden++; }
        }
    }

    // warp reduce
    #pragma unroll
    for (int o = 16; o > 0; o >>= 1) {
        lnum += __shfl_down_sync(0xffffffffu, lnum, o);
        lden += __shfl_down_sync(0xffffffffu, lden, o);
    }
    __shared__ float snum[TPB / 32];
    __shared__ int   sden[TPB / 32];
    int wid = tid >> 5;
    if ((tid & 31) == 0) { snum[wid] = lnum; sden[wid] = lden; }
    __syncthreads();
    if (tid == 0) {
        float bn = 0.0f; int bd = 0;
        #pragma unroll
        for (int k = 0; k < TPB / 32; k++) { bn += snum[k]; bd += sden[k]; }
        if (bn != 0.0f) atomicAdd(&g_num, (double)bn);
        if (bd != 0)    atomicAdd(&g_den, (double)bd);
        __threadfence();
        unsigned ticket = atomicAdd(&g_done, 1u);
        if (ticket == gridDim.x - 1) {
            __threadfence();
            double num = *((volatile double*)&g_num);
            double den = *((volatile double*)&g_den);
            if (den < 1.0) den = 1.0;
            if (has_loss) out_loss[0] = (float)(num / den);
            g_num = 0.0;
            g_den = 0.0;
            g_mask4 = 0;
            g_done = 0u;
        }
    }
}

// ---------------------------------------------------------------------------
extern "C" void kernel_launch(void* const* d_in, const int* in_sizes, int n_in,
                              void* d_out, int out_size)
{
    const float* pred   = (const float*)d_in[0];
    const float* target = (const float*)d_in[1];
    const void*  pos    = d_in[2];
    int n = in_sizes[2];               // pos_idx element count = B*A*W*H

    float* out = (float*)d_out;
    int has_loss = (out_size > n) ? 1 : 0;
    float* out_iou = out + (has_loss ? 1 : 0);

    rot_detect_kernel<<<192, 256>>>((const unsigned char*)pos, n);

    int blocks = (n + EPB - 1) / EPB;
    rot_iou_kernel<<<blocks, TPB>>>(pred, target, pos, out, out_iou,
                                    n, has_loss);
}

// round 12
// speedup vs baseline: 3.8667x; 1.0200x over previous
#include <cuda_runtime.h>

#define EPSF 1e-8f
#define DEG2RAD 0.017453292519943295f

#define TPB   256
#define EPT   4                  // elements per thread
#define EPB   (TPB * EPT)        // 1024 elements per block

__device__ double   g_num;    // zero-init; self-reset by last block each call
__device__ double   g_den;
__device__ int      g_mask4;
__device__ unsigned g_done;

// ---------------------------------------------------------------------------
// Kernel 1: detect pos_idx storage layout by scanning the first n BYTES
// (safe for u8 / i32 / f32 backing buffers).
//   residue pattern 0b0001 -> int32 {0,1}
//   residue pattern 0b1100 -> float32 {0.0,1.0}
//   anything else / all-zero -> uint8/bool fallback
// ---------------------------------------------------------------------------
__global__ void rot_detect_kernel(const unsigned char* __restrict__ p, int nbytes) {
    int nw = nbytes >> 2;
    const unsigned* w = (const unsigned*)p;
    unsigned pat = 0;
    for (int idx = blockIdx.x * blockDim.x + threadIdx.x; idx < nw;
         idx += gridDim.x * blockDim.x) {
        unsigned v = w[idx];
        if (v & 0x000000FFu) pat |= 1u;
        if (v & 0x0000FF00u) pat |= 2u;
        if (v & 0x00FF0000u) pat |= 4u;
        if (v & 0xFF000000u) pat |= 8u;
    }
    #pragma unroll
    for (int o = 16; o > 0; o >>= 1)
        pat |= __shfl_down_sync(0xffffffffu, pat, o);
    if ((threadIdx.x & 31) == 0 && pat)
        atomicOr(&g_mask4, (int)pat);
}

// ---------------------------------------------------------------------------
// SCALED slab clip, midpoint/half-span form. Arguments:
//   tx = px*kx, ty = py*ky  (signed products for this edge)
//   hsx = Wb*|kx|, hsy = Hb*|ky|  (pair-invariant half-spans, hoisted)
//   s = |kx'|*|ky'| scale (t in [0,s])
// Interval on x-axis is [-tx-hsx, -tx+hsx]; same for y. Division-free.
// ---------------------------------------------------------------------------
__device__ __forceinline__ float seg_dts(float tx, float ty,
                                         float hsx, float hsy, float s)
{
    float t0 = fmaxf(fmaxf(-(tx + hsx), -(ty + hsy)), 0.0f);
    float t1 = fminf(fminf(hsx - tx, hsy - ty), s);
    return fmaxf(t1 - t0, 0.0f);
}

// ---------------------------------------------------------------------------
// One rotated-IoU: frame-local scaled slab clipping + Green's theorem.
// ---------------------------------------------------------------------------
__device__ __forceinline__ float compute_iou(float x1, float y1, float w1,
                                             float h1, float a1raw,
                                             float x2, float y2, float w2,
                                             float h2, float a2raw)
{
    float a1 = a1raw * DEG2RAD;
    float a2 = (a2raw * 180.0f - 180.0f) * DEG2RAD;

    float W1 = 0.5f * w1, H1 = 0.5f * h1;
    float W2 = 0.5f * w2, H2 = 0.5f * h2;

    float sd, cd, s2, c2;
    __sincosf(a1 - a2, &sd, &cd);
    __sincosf(a2,      &s2, &c2);
    float dx = x1 - x2, dy = y1 - y2;
    float ux =  c2 * dx + s2 * dy;
    float uy = -s2 * dx + c2 * dy;

    // box1 edge vectors / corners (CCW) in box2 frame
    float exx =  w1 * cd, exy = w1 * sd;
    float eyx = -h1 * sd, eyy = h1 * cd;
    float a0x = ux + 0.5f * (exx + eyx), a0y = uy + 0.5f * (exy + eyy);
    float b1x = a0x - exx, b1y = a0y - exy;
    float b2x = b1x - eyx, b2y = b1y - eyy;
    float b3x = a0x - eyx, b3y = a0y - eyy;

    // shared factors: |edge| products reduce to kappa = |sd*cd|
    float ts = fabsf(sd), tc = fabsf(cd);
    float kap = ts * tc;
    float alp = copysignf(ts, cd);    // |sd| * sgn(cd)
    float bet = copysignf(tc, sd);    // |cd| * sgn(sd)

    // signed per-pair direction factors
    float kxA = w1 * alp, kyA = w1 * bet;      // edges +-ex of box1
    float kxB = -h1 * bet, kyB = h1 * alp;     // edges +-ey of box1
    float sA = (w1 * w1) * kap;
    float sB = (h1 * h1) * kap;
    // pair-invariant half-spans against box2 slab [+-W2]x[+-H2]
    float hsAx = W2 * (w1 * ts), hsAy = H2 * (w1 * tc);
    float hsBx = W2 * (h1 * tc), hsBy = H2 * (h1 * ts);

    // half 1: box1 edges clipped by box2 slab; contribution cross(p,r)*dt
    float dts0 = seg_dts(-(a0x * kxA), -(a0y * kyA), hsAx, hsAy, sA);
    float dts1 = seg_dts(-(b1x * kxB), -(b1y * kyB), hsBx, hsBy, sB);
    float dts2 = seg_dts( (b2x * kxA),  (b2y * kyA), hsAx, hsAy, sA);
    float dts3 = seg_dts( (b3x * kxB),  (b3y * kyB), hsBx, hsBy, sB);
    float c0  = a0y * exx - a0x * exy;
    float c1  = b1y * eyx - b1x * eyy;
    float c2c = b2x * exy - b2y * exx;
    float c3  = b3x * eyy - b3y * eyx;
    float PA = c0 * dts0 + c2c * dts2;
    float PB = c1 * dts1 + c3 * dts3;
    float acc1 = __fdividef(PA * sB + PB * sA, fmaxf(sA * sB, 1e-35f));

    // half 2: box2 edges clipped by box1 slab (box1 frame);
    // every box2 edge contributes the constant cross w2*h2/2 per unit dt
    float qx = W2 - ux, qy = H2 - uy;
    float g0u =  cd * qx + sd * qy;
    float g0v = -sd * qx + cd * qy;
    float fxu = cd * w2, fxv = -sd * w2;
    float fyu = sd * h2, fyv =  cd * h2;
    float g1u = g0u - fxu, g1v = g0v - fxv;
    float g2u = g1u - fyu, g2v = g1v - fyv;
    float g3u = g0u - fyu, g3v = g0v - fyv;
    float kxC = w2 * alp, kyC = -w2 * bet;
    float kxD = h2 * bet, kyD =  h2 * alp;
    float sC = (w2 * w2) * kap;
    float sD = (h2 * h2) * kap;
    float hsCx = W1 * (w2 * ts), hsCy = H1 * (w2 * tc);
    float hsDx = W1 * (h2 * tc), hsDy = H1 * (h2 * ts);
    float e0 = seg_dts(-(g0u * kxC), -(g0v * kyC), hsCx, hsCy, sC);
    float e1 = seg_dts(-(g1u * kxD), -(g1v * kyD), hsDx, hsDy, sD);
    float e2 = seg_dts( (g2u * kxC),  (g2v * kyC), hsCx, hsCy, sC);
    float e3 = seg_dts( (g3u * kxD),  (g3v * kyD), hsDx, hsDy, sD);
    float SC = e0 + e2, SD = e1 + e3;
    float sum2 = __fdividef(SC * sD + SD * sC, fmaxf(sC * sD, 1e-35f));

    float inter = fmaxf(0.5f * acc1 + (0.25f * w2 * h2) * sum2, 0.0f);
    float iou = __fdividef(inter, w1 * h1 + w2 * h2 - inter + EPSF);
    return fminf(fmaxf(iou, 1e-7f), 1.0f - 1e-7f);
}

// ---------------------------------------------------------------------------
// Kernel 2: main — smem-staged coalesced loads, 4 elements/thread serial
// compute, single-wave grid, fused loss reduction + last-block finalize
// (self-resets device state for graph replay determinism).
// ---------------------------------------------------------------------------
__global__ void __launch_bounds__(TPB, 5)
rot_iou_kernel(const float* __restrict__ pred,
               const float* __restrict__ target,
               const void*  __restrict__ pos,
               float* __restrict__ out_loss,
               float* __restrict__ out_iou,
               int n, int has_loss)
{
    __shared__ float sp[EPB * 5];     // 20 KB
    __shared__ float st[EPB * 5];     // 20 KB

    int tid = threadIdx.x;
    int e0  = blockIdx.x * EPB;       // first element of this block
    int cnt = n - e0;
    if (cnt > EPB) cnt = EPB;
    int m4 = g_mask4;

    // ---- stage pred/target tiles with coalesced loads ----
    if (cnt == EPB) {
        // full tile: 5120 floats = 1280 float4 per array (1280/TPB = 5 exact)
        const float4* P = (const float4*)(pred   + (size_t)e0 * 5);
        const float4* T = (const float4*)(target + (size_t)e0 * 5);
        float4* SP = (float4*)sp;
        float4* ST = (float4*)st;
        #pragma unroll
        for (int k = 0; k < 5; k++) {
            int idx = tid + k * TPB;
            SP[idx] = P[idx];
            ST[idx] = T[idx];
        }
    } else if (cnt > 0) {
        int nf = cnt * 5;
        const float* P = pred   + (size_t)e0 * 5;
        const float* T = target + (size_t)e0 * 5;
        for (int idx = tid; idx < nf; idx += TPB) {
            sp[idx] = P[idx];
            st[idx] = T[idx];
        }
    }
    __syncthreads();

    float lnum = 0.0f;
    int   lden = 0;

    #pragma unroll
    for (int j = 0; j < EPT; j++) {
        int el = tid + j * TPB;        // local element (stride-TPB sets)
        int e  = e0 + el;
        if (el < cnt) {
            const float* pb = sp + 5 * el;
            const float* tb = st + 5 * el;
            float iou = compute_iou(pb[0], pb[1], pb[2], pb[3], pb[4],
                                    tb[0], tb[1], tb[2], tb[3], tb[4]);
            out_iou[e] = iou;
            bool mm;
            if (m4 == 1)       mm = (((const int*)pos)[e] != 0);
            else if (m4 == 12) mm = (((const float*)pos)[e] != 0.0f);
            else               mm = (((const unsigned char*)pos)[e] != 0);
            if (mm) { lnum += 1.0f - iou; lden++; }
        }
    }

    // warp reduce
    #pragma unroll
    for (int o = 16; o > 0; o >>= 1) {
        lnum += __shfl_down_sync(0xffffffffu, lnum, o);
        lden += __shfl_down_sync(0xffffffffu, lden, o);
    }
    __shared__ float snum[TPB / 32];
    __shared__ int   sden[TPB / 32];
    int wid = tid >> 5;
    if ((tid & 31) == 0) { snum[wid] = lnum; sden[wid] = lden; }
    __syncthreads();
    if (tid == 0) {
        float bn = 0.0f; int bd = 0;
        #pragma unroll
        for (int k = 0; k < TPB / 32; k++) { bn += snum[k]; bd += sden[k]; }
        if (bn != 0.0f) atomicAdd(&g_num, (double)bn);
        if (bd != 0)    atomicAdd(&g_den, (double)bd);
        __threadfence();
        unsigned ticket = atomicAdd(&g_done, 1u);
        if (ticket == gridDim.x - 1) {
            __threadfence();
            double num = *((volatile double*)&g_num);
            double den = *((volatile double*)&g_den);
            if (den < 1.0) den = 1.0;
            if (has_loss) out_loss[0] = (float)(num / den);
            g_num = 0.0;
            g_den = 0.0;
            g_mask4 = 0;
            g_done = 0u;
        }
    }
}

// ---------------------------------------------------------------------------
extern "C" void kernel_launch(void* const* d_in, const int* in_sizes, int n_in,
                              void* d_out, int out_size)
{
    const float* pred   = (const float*)d_in[0];
    const float* target = (const float*)d_in[1];
    const void*  pos    = d_in[2];
    int n = in_sizes[2];               // pos_idx element count = B*A*W*H

    float* out = (float*)d_out;
    int has_loss = (out_size > n) ? 1 : 0;
    float* out_iou = out + (has_loss ? 1 : 0);

    rot_detect_kernel<<<192, 256>>>((const unsigned char*)pos, n);

    int blocks = (n + EPB - 1) / EPB;
    rot_iou_kernel<<<blocks, TPB>>>(pred, target, pos, out, out_iou,
                                    n, has_loss);
}